// round 12
// baseline (speedup 1.0000x reference)
#include <cuda_runtime.h>
#include <cuda_fp16.h>
#include <math.h>
#include <stdint.h>

// ---------------- Problem constants ----------------
#define LSEQ   2048
#define DMODEL 4096
#define NH     128
#define DP     64
#define NG     8
#define DN     128
#define CSZ    128
#define NCH    (LSEQ / CSZ)
#define KCONV  4
#define DINTER 8192
#define DCONV  10240
#define DPROJ  18560
#define RMS_EPS 1e-5f

// ---------------- Scratch ----------------
__device__ float g_proj[LSEQ * DPROJ];
__device__ float g_xbc[LSEQ * DCONV];
__device__ float g_dt[LSEQ * NH];
__device__ float g_acs[NCH * NH * CSZ];
__device__ float g_alast[NCH * NH];
__device__ float g_cbt[NCH * NG * CSZ * CSZ];
__device__ float g_states[NCH * NH * DP * DN];
__device__ float g_prefix[NCH * NH * DP * DN];
__device__ float g_y[LSEQ * DINTER];
// fp16 copies of GEMM operands
__device__ __half g_hsth[LSEQ * DMODEL];
__device__ __half g_w1th[DPROJ * DMODEL];
__device__ __half g_w2th[DMODEL * DINTER];
__device__ __half g_yh[LSEQ * DINTER];

// ---------------- helpers ----------------
__device__ __forceinline__ void mma_f16(float c[4], const uint32_t a[4], const uint32_t b[2]) {
    asm volatile(
        "mma.sync.aligned.m16n8k16.row.col.f32.f16.f16.f32 "
        "{%0,%1,%2,%3}, {%4,%5,%6,%7}, {%8,%9}, {%0,%1,%2,%3};"
        : "+f"(c[0]), "+f"(c[1]), "+f"(c[2]), "+f"(c[3])
        : "r"(a[0]), "r"(a[1]), "r"(a[2]), "r"(a[3]), "r"(b[0]), "r"(b[1]));
}
__device__ __forceinline__ void ldsm_x4(uint32_t& r0, uint32_t& r1, uint32_t& r2, uint32_t& r3,
                                        uint32_t addr) {
    asm volatile("ldmatrix.sync.aligned.m8n8.x4.shared.b16 {%0,%1,%2,%3}, [%4];"
                 : "=r"(r0), "=r"(r1), "=r"(r2), "=r"(r3) : "r"(addr));
}
__device__ __forceinline__ float fast_silu(float x) {
    float t;
    asm("tanh.approx.f32 %0, %1;" : "=f"(t) : "f"(x * 0.5f));
    return 0.5f * x * (1.f + t);
}
__device__ __forceinline__ uint32_t smem_u32(const void* p) {
    uint32_t a;
    asm("{ .reg .u64 t; cvta.to.shared.u64 t, %1; cvt.u32.u64 %0, t; }" : "=r"(a) : "l"(p));
    return a;
}
__device__ __forceinline__ void cp_async16(uint32_t saddr, const void* gaddr) {
    asm volatile("cp.async.cg.shared.global [%0], [%1], 16;" :: "r"(saddr), "l"(gaddr));
}
#define CP_COMMIT() asm volatile("cp.async.commit_group;" ::: "memory")
#define CP_WAIT(n)  asm volatile("cp.async.wait_group %0;" :: "n"(n) : "memory")

// ---------------- fp32 -> fp16 pre-conversion ----------------
__global__ void cvt_f16_kernel(const float* __restrict__ in, __half* __restrict__ out, int n4)
{
    int i = blockIdx.x * blockDim.x + threadIdx.x;
    if (i >= n4) return;
    float4 v = ((const float4*)in)[i];
    __half2 h0 = __floats2half2_rn(v.x, v.y);
    __half2 h1 = __floats2half2_rn(v.z, v.w);
    uint2 o;
    o.x = *(uint32_t*)&h0;
    o.y = *(uint32_t*)&h1;
    ((uint2*)out)[i] = o;
}

// ---------------- fp16 GEMM: ldmatrix fragment loads, warp tile 64x64, BK=64, 3 stages ----------------
// C[M,Nd] = A[M,Kd]*B[Nd,Kd]^T. grid.x = M tiles (fast) for L2 reuse of B.
#define GSTAGES 3
#define STAGEW  (128 * 32)
#define GEMM_DSMEM (GSTAGES * 2 * STAGEW * 4)   // 98304 bytes

__global__ __launch_bounds__(128, 2) void gemm_f16_kernel(
    const __half* __restrict__ A, const __half* __restrict__ B, float* __restrict__ C,
    int Nd, int Kd)
{
    extern __shared__ float smf[];
    float* const Abuf = smf;
    float* const Bbuf = smf + GSTAGES * STAGEW;

    const int tid  = threadIdx.x;
    const int lane = tid & 31, warp = tid >> 5;
    const int wm = (warp >> 1) * 64;
    const int wn = (warp & 1) * 64;
    const int g  = lane >> 2, tq = lane & 3;
    const int bm = blockIdx.x * 128, bn = blockIdx.y * 128;   // M fast, N slow

    // staging geometry
    const int r0 = tid >> 3, c = tid & 7;
    const uint32_t swoff = (uint32_t)((c ^ (r0 & 7)) << 4);
    const __half* AgBase = A + (size_t)(bm + r0) * Kd + c * 8;
    const __half* BgBase = B + (size_t)(bn + r0) * Kd + c * 8;
    const uint32_t uA = smem_u32(Abuf);
    const uint32_t uB = smem_u32(Bbuf);
    const uint32_t sA0 = uA + (uint32_t)(r0 * 128) + swoff;
    const uint32_t sB0 = uB + (uint32_t)(r0 * 128) + swoff;

    // ldmatrix per-lane geometry: matrices ordered (rowblk0,c0),(rowblk1,c0),(rowblk0,c1),(rowblk1,c1)
    const int r7   = lane & 7;
    const int ri   = r7 | (((lane >> 3) & 1) << 3);   // row within 16-row block
    const int csel = lane >> 4;                        // chunk select (c0/c1)
    const uint32_t rowA = (uint32_t)((wm + ri) * 128);
    const uint32_t rowB = (uint32_t)((wn + ri) * 128);

    const int KT = Kd >> 6;

#pragma unroll
    for (int s = 0; s < GSTAGES - 1; s++) {
        const uint32_t so = (uint32_t)(s * STAGEW * 4);
        const size_t ko = (size_t)s * 64;
#pragma unroll
        for (int j = 0; j < 8; j++) {
            cp_async16(sA0 + so + j * 16 * 128, AgBase + (size_t)(16 * j) * Kd + ko);
            cp_async16(sB0 + so + j * 16 * 128, BgBase + (size_t)(16 * j) * Kd + ko);
        }
        CP_COMMIT();
    }

    float acc[4][8][4];
#pragma unroll
    for (int mt = 0; mt < 4; mt++)
#pragma unroll
        for (int nt = 0; nt < 8; nt++)
#pragma unroll
            for (int qq = 0; qq < 4; qq++) acc[mt][nt][qq] = 0.f;

    int buf = 0;
    for (int kt = 0; kt < KT; kt++) {
        CP_WAIT(1);
        __syncthreads();

        const int pf = kt + GSTAGES - 1;
        if (pf < KT) {
            const int pb = pf % GSTAGES;
            const uint32_t so = (uint32_t)(pb * STAGEW * 4);
            const size_t ko = (size_t)pf * 64;
#pragma unroll
            for (int j = 0; j < 8; j++) {
                cp_async16(sA0 + so + j * 16 * 128, AgBase + (size_t)(16 * j) * Kd + ko);
                cp_async16(sB0 + so + j * 16 * 128, BgBase + (size_t)(16 * j) * Kd + ko);
            }
        }
        CP_COMMIT();

        const uint32_t uAb = uA + (uint32_t)(buf * (STAGEW * 4));
        const uint32_t uBb = uB + (uint32_t)(buf * (STAGEW * 4));
#pragma unroll
        for (int ks = 0; ks < 4; ks++) {
            const uint32_t koff = (uint32_t)(((2 * ks + csel) ^ r7) << 4);
            const uint32_t aA = uAb + rowA + koff;
            const uint32_t aB = uBb + rowB + koff;
            uint32_t af[4][4], bf[8][2];
#pragma unroll
            for (int mt = 0; mt < 4; mt++)
                ldsm_x4(af[mt][0], af[mt][1], af[mt][2], af[mt][3], aA + mt * 2048);
#pragma unroll
            for (int p = 0; p < 4; p++)
                ldsm_x4(bf[2 * p][0], bf[2 * p + 1][0], bf[2 * p][1], bf[2 * p + 1][1],
                        aB + p * 2048);
#pragma unroll
            for (int mt = 0; mt < 4; mt++)
#pragma unroll
                for (int nt = 0; nt < 8; nt++)
                    mma_f16(acc[mt][nt], af[mt], bf[nt]);
        }
        buf = (buf + 1) % GSTAGES;
    }

#pragma unroll
    for (int mt = 0; mt < 4; mt++) {
#pragma unroll
        for (int nt = 0; nt < 8; nt++) {
            const int row = bm + wm + mt * 16 + g;
            const int col = bn + wn + nt * 8 + 2 * tq;
            *(float2*)&C[(size_t)row * Nd + col]       = make_float2(acc[mt][nt][0], acc[mt][nt][1]);
            *(float2*)&C[(size_t)(row + 8) * Nd + col] = make_float2(acc[mt][nt][2], acc[mt][nt][3]);
        }
    }
}

// ---------------- Depthwise causal conv (K=4) + SiLU ----------------
__global__ void conv_silu_kernel(const float* __restrict__ conv_w, const float* __restrict__ conv_b)
{
    int idx = blockIdx.x * blockDim.x + threadIdx.x;
    if (idx >= LSEQ * DCONV) return;
    int t = idx / DCONV, c = idx % DCONV;
    float acc = conv_b[c];
    const float* w = conv_w + c * KCONV;
#pragma unroll
    for (int k = 0; k < KCONV; k++) {
        int tt = t + k - (KCONV - 1);
        if (tt >= 0) acc += w[k] * g_proj[(size_t)tt * DPROJ + DINTER + c];
    }
    g_xbc[idx] = fast_silu(acc);
}

// ---------------- dt softplus + per-chunk cumsum of A*dt ----------------
__global__ __launch_bounds__(CSZ) void dt_scan_kernel(
    const float* __restrict__ dt_bias, const float* __restrict__ A_log)
{
    int c = blockIdx.x, h = blockIdx.y, l = threadIdx.x;
    int t = c * CSZ + l;
    float raw = g_proj[(size_t)t * DPROJ + DINTER + DCONV + h] + dt_bias[h];
    float dtp = (raw > 0.f) ? (raw + log1pf(__expf(-raw))) : log1pf(__expf(raw));
    g_dt[t * NH + h] = dtp;
    float a = -__expf(A_log[h]) * dtp;

    __shared__ float s[CSZ];
    s[l] = a;
    __syncthreads();
#pragma unroll
    for (int off = 1; off < CSZ; off <<= 1) {
        float v = (l >= off) ? s[l - off] : 0.f;
        __syncthreads();
        s[l] += v;
        __syncthreads();
    }
    g_acs[(c * NH + h) * CSZ + l] = s[l];
    if (l == CSZ - 1) g_alast[c * NH + h] = s[l];
}

// ---------------- CBt[c][g][s][l] = sum_n C[l,n]*B[s,n] ----------------
__global__ __launch_bounds__(256) void cb_kernel()
{
    int c = blockIdx.x, g = blockIdx.y;
    int tid = threadIdx.x, tx = tid & 15, ty = tid >> 4;
    __shared__ float Csn[16][CSZ];
    __shared__ float Bsn[16][CSZ];
    float acc[8][8];
#pragma unroll
    for (int i = 0; i < 8; i++)
#pragma unroll
        for (int j = 0; j < 8; j++) acc[i][j] = 0.f;

    const float* Cg = g_xbc + DINTER + NG * DN + g * DN;
    const float* Bg = g_xbc + DINTER + g * DN;

    for (int n0 = 0; n0 < DN; n0 += 16) {
        for (int i = tid; i < CSZ * 4; i += 256) {
            int r = i >> 2, q = i & 3;
            const size_t row = (size_t)(c * CSZ + r) * DCONV + n0 + q * 4;
            float4 cv = *(const float4*)(Cg + row);
            float4 bv = *(const float4*)(Bg + row);
            Csn[q * 4 + 0][r] = cv.x; Csn[q * 4 + 1][r] = cv.y;
            Csn[q * 4 + 2][r] = cv.z; Csn[q * 4 + 3][r] = cv.w;
            Bsn[q * 4 + 0][r] = bv.x; Bsn[q * 4 + 1][r] = bv.y;
            Bsn[q * 4 + 2][r] = bv.z; Bsn[q * 4 + 3][r] = bv.w;
        }
        __syncthreads();
#pragma unroll
        for (int nn = 0; nn < 16; nn++) {
            float4 c0 = *(const float4*)&Csn[nn][tx * 8];
            float4 c1 = *(const float4*)&Csn[nn][tx * 8 + 4];
            float4 b0 = *(const float4*)&Bsn[nn][ty * 8];
            float4 b1 = *(const float4*)&Bsn[nn][ty * 8 + 4];
            float cl[8] = {c0.x, c0.y, c0.z, c0.w, c1.x, c1.y, c1.z, c1.w};
            float bs[8] = {b0.x, b0.y, b0.z, b0.w, b1.x, b1.y, b1.z, b1.w};
#pragma unroll
            for (int si = 0; si < 8; si++)
#pragma unroll
                for (int li = 0; li < 8; li++) acc[si][li] += cl[li] * bs[si];
        }
        __syncthreads();
    }
    float* out = g_cbt + (size_t)(c * NG + g) * CSZ * CSZ;
#pragma unroll
    for (int si = 0; si < 8; si++) {
        int s = ty * 8 + si;
        *(float4*)(out + (size_t)s * CSZ + tx * 8)     = make_float4(acc[si][0], acc[si][1], acc[si][2], acc[si][3]);
        *(float4*)(out + (size_t)s * CSZ + tx * 8 + 4) = make_float4(acc[si][4], acc[si][5], acc[si][6], acc[si][7]);
    }
}

// ---------------- Y_diag + D residual (factorized decay exps) ----------------
__global__ __launch_bounds__(256) void ydiag_kernel(const float* __restrict__ Dparam)
{
    int c = blockIdx.x, h = blockIdx.y, g = h >> 4;
    int tid = threadIdx.x, tx = tid & 15, ty = tid >> 4;
    __shared__ float xs[CSZ][DP];
    __shared__ float Ms[CSZ][17];
    __shared__ float acsS[CSZ];
    __shared__ float dts[CSZ];
    __shared__ float el[CSZ];
    __shared__ float esd[16];

    for (int i = tid; i < CSZ * DP / 4; i += 256) {
        int r = i >> 4, q = i & 15;
        *(float4*)&xs[r][q * 4] =
            *(const float4*)(g_xbc + (size_t)(c * CSZ + r) * DCONV + h * DP + q * 4);
    }
    if (tid < CSZ) {
        dts[tid]  = g_dt[(c * CSZ + tid) * NH + h];
        acsS[tid] = g_acs[(c * NH + h) * CSZ + tid];
    }
    __syncthreads();

    float acc[8][4];
#pragma unroll
    for (int i = 0; i < 8; i++)
#pragma unroll
        for (int j = 0; j < 4; j++) acc[i][j] = 0.f;

    const float* cbBase = g_cbt + (size_t)(c * NG + g) * CSZ * CSZ;
    const int ss_row = tid >> 4;
    const int lg     = tid & 15;

    for (int s0 = 0; s0 < CSZ; s0 += 16) {
        const float a0 = acsS[s0];
        if (tid < CSZ) el[tid] = __expf(acsS[tid] - a0);
        else if (tid < CSZ + 16) {
            int s = s0 + (tid - CSZ);
            esd[tid - CSZ] = __expf(a0 - acsS[s]) * dts[s];
        }
        __syncthreads();

        {
            const int s = s0 + ss_row;
            const float fs = esd[ss_row];
            const float* cbRow = cbBase + (size_t)s * CSZ;
#pragma unroll
            for (int k = 0; k < 8; k++) {
                const int l = lg * 8 + k;
                Ms[l][ss_row] = (s <= l) ? cbRow[l] * el[l] * fs : 0.f;
            }
        }
        __syncthreads();

#pragma unroll
        for (int ss = 0; ss < 16; ss++) {
            const int s = s0 + ss;
            float msv[8];
#pragma unroll
            for (int i = 0; i < 8; i++) msv[i] = Ms[ty * 8 + i][ss];
            float4 xv4 = *(const float4*)&xs[s][tx * 4];
#pragma unroll
            for (int i = 0; i < 8; i++) {
                acc[i][0] += msv[i] * xv4.x;
                acc[i][1] += msv[i] * xv4.y;
                acc[i][2] += msv[i] * xv4.z;
                acc[i][3] += msv[i] * xv4.w;
            }
        }
        __syncthreads();
    }

    const float dcoef = Dparam[h];
#pragma unroll
    for (int i = 0; i < 8; i++) {
        int l = ty * 8 + i;
        float4 xr = *(const float4*)&xs[l][tx * 4];
        float4 o = make_float4(acc[i][0] + dcoef * xr.x, acc[i][1] + dcoef * xr.y,
                               acc[i][2] + dcoef * xr.z, acc[i][3] + dcoef * xr.w);
        *(float4*)(g_y + (size_t)(c * CSZ + l) * DINTER + h * DP + tx * 4) = o;
    }
}

// ---------------- Local chunk states ----------------
__global__ __launch_bounds__(256) void states_kernel()
{
    int c = blockIdx.x, h = blockIdx.y, g = h >> 4;
    int tid = threadIdx.x, tx = tid & 15, ty = tid >> 4;
    __shared__ float Bsh[32][DN];
    __shared__ float xds[32][DP];
    __shared__ float dec[32];
    float acc[4][8];
#pragma unroll
    for (int i = 0; i < 4; i++)
#pragma unroll
        for (int j = 0; j < 8; j++) acc[i][j] = 0.f;

    const float al = g_alast[c * NH + h];
    for (int l0 = 0; l0 < CSZ; l0 += 32) {
        for (int i = tid; i < 32 * DN / 4; i += 256) {
            int r = i >> 5, q = i & 31;
            *(float4*)&Bsh[r][q * 4] = *(const float4*)(
                g_xbc + (size_t)(c * CSZ + l0 + r) * DCONV + DINTER + g * DN + q * 4);
        }
        for (int i = tid; i < 32 * DP / 4; i += 256) {
            int r = i >> 4, q = i & 15;
            int t = c * CSZ + l0 + r;
            float4 xv = *(const float4*)(g_xbc + (size_t)t * DCONV + h * DP + q * 4);
            float d = g_dt[t * NH + h];
            xv.x *= d; xv.y *= d; xv.z *= d; xv.w *= d;
            *(float4*)&xds[r][q * 4] = xv;
        }
        if (tid < 32) dec[tid] = __expf(al - g_acs[(c * NH + h) * CSZ + l0 + tid]);
        __syncthreads();
#pragma unroll 8
        for (int ll = 0; ll < 32; ll++) {
            float d = dec[ll];
            float4 b0 = *(const float4*)&Bsh[ll][tx * 8];
            float4 b1 = *(const float4*)&Bsh[ll][tx * 8 + 4];
            float bb[8] = {b0.x, b0.y, b0.z, b0.w, b1.x, b1.y, b1.z, b1.w};
            float4 xv = *(const float4*)&xds[ll][ty * 4];
            float xp[4] = {xv.x * d, xv.y * d, xv.z * d, xv.w * d};
#pragma unroll
            for (int pi = 0; pi < 4; pi++)
#pragma unroll
                for (int nj = 0; nj < 8; nj++) acc[pi][nj] += xp[pi] * bb[nj];
        }
        __syncthreads();
    }
    float* out = g_states + (size_t)(c * NH + h) * DP * DN;
#pragma unroll
    for (int pi = 0; pi < 4; pi++) {
        int p = ty * 4 + pi;
        *(float4*)(out + (size_t)p * DN + tx * 8)     = make_float4(acc[pi][0], acc[pi][1], acc[pi][2], acc[pi][3]);
        *(float4*)(out + (size_t)p * DN + tx * 8 + 4) = make_float4(acc[pi][4], acc[pi][5], acc[pi][6], acc[pi][7]);
    }
}

// ---------------- Inter-chunk scan ----------------
__global__ void prefix_kernel()
{
    int idx = blockIdx.x * blockDim.x + threadIdx.x;
    if (idx >= NH * DP * DN) return;
    int h = idx >> 13;
    float s = 0.f;
#pragma unroll
    for (int c = 0; c < NCH; c++) {
        size_t off = (size_t)c * NH * DP * DN + idx;
        g_prefix[off] = s;
        s = __expf(g_alast[c * NH + h]) * s + g_states[off];
    }
}

// ---------------- Y_off ----------------
__global__ __launch_bounds__(256) void yoff_kernel()
{
    int c = blockIdx.x, h = blockIdx.y, g = h >> 4;
    int tid = threadIdx.x, tx = tid & 15, ty = tid >> 4;
    __shared__ float Cs[CSZ][32];
    __shared__ float Pf[DP][33];
    __shared__ float acsS[CSZ];
    if (tid < CSZ) acsS[tid] = g_acs[(c * NH + h) * CSZ + tid];

    float acc[8][4];
#pragma unroll
    for (int i = 0; i < 8; i++)
#pragma unroll
        for (int j = 0; j < 4; j++) acc[i][j] = 0.f;

    for (int n0 = 0; n0 < DN; n0 += 32) {
        for (int i = tid; i < CSZ * 8; i += 256) {
            int r = i >> 3, q = i & 7;
            *(float4*)&Cs[r][q * 4] = *(const float4*)(
                g_xbc + (size_t)(c * CSZ + r) * DCONV + DINTER + NG * DN + g * DN + n0 + q * 4);
        }
        for (int i = tid; i < DP * 8; i += 256) {
            int r = i >> 3, q = i & 7;
            float4 v = *(const float4*)(
                g_prefix + ((size_t)(c * NH + h) * DP + r) * DN + n0 + q * 4);
            Pf[r][q * 4 + 0] = v.x; Pf[r][q * 4 + 1] = v.y;
            Pf[r][q * 4 + 2] = v.z; Pf[r][q * 4 + 3] = v.w;
        }
        __syncthreads();
#pragma unroll 8
        for (int nn = 0; nn < 32; nn++) {
            float cl[8], pv[4];
#pragma unroll
            for (int i = 0; i < 8; i++) cl[i] = Cs[ty * 8 + i][nn];
#pragma unroll
            for (int j = 0; j < 4; j++) pv[j] = Pf[tx * 4 + j][nn];
#pragma unroll
            for (int i = 0; i < 8; i++)
#pragma unroll
                for (int j = 0; j < 4; j++) acc[i][j] += cl[i] * pv[j];
        }
        __syncthreads();
    }
#pragma unroll
    for (int i = 0; i < 8; i++) {
        int l = ty * 8 + i;
        float e = __expf(acsS[l]);
        float* yp = g_y + (size_t)(c * CSZ + l) * DINTER + h * DP + tx * 4;
        float4 y = *(float4*)yp;
        y.x += e * acc[i][0]; y.y += e * acc[i][1];
        y.z += e * acc[i][2]; y.w += e * acc[i][3];
        *(float4*)yp = y;
    }
}

// ---------------- RMSNorm * norm_w * silu(gate); emits fp16 for GEMM2 ----------------
__global__ __launch_bounds__(256) void rms_gate_kernel(const float* __restrict__ norm_w)
{
    int t = blockIdx.x, tid = threadIdx.x;
    const size_t base = (size_t)t * DINTER;
    float ss = 0.f;
    for (int i = tid; i < DINTER; i += 256) {
        float v = g_y[base + i];
        ss += v * v;
    }
    __shared__ float red[256];
    red[tid] = ss;
    __syncthreads();
#pragma unroll
    for (int o = 128; o > 0; o >>= 1) {
        if (tid < o) red[tid] += red[tid + o];
        __syncthreads();
    }
    float inv = rsqrtf(red[0] / (float)DINTER + RMS_EPS);
    for (int i = tid; i < DINTER; i += 256) {
        float v = g_y[base + i] * inv * norm_w[i];
        v *= fast_silu(g_proj[(size_t)t * DPROJ + i]);
        g_yh[base + i] = __float2half_rn(v);
    }
}

// ---------------- Launch ----------------
extern "C" void kernel_launch(void* const* d_in, const int* in_sizes, int n_in,
                              void* d_out, int out_size)
{
    (void)in_sizes; (void)n_in; (void)out_size;
    const float* hs         = (const float*)d_in[0];
    const float* in_proj_w  = (const float*)d_in[1];
    const float* conv_w     = (const float*)d_in[2];
    const float* conv_b     = (const float*)d_in[3];
    const float* dt_bias    = (const float*)d_in[4];
    const float* A_log      = (const float*)d_in[5];
    const float* Dp         = (const float*)d_in[6];
    const float* norm_w     = (const float*)d_in[7];
    const float* out_proj_w = (const float*)d_in[8];
    float* out = (float*)d_out;

    void *p_proj = nullptr, *p_yh = nullptr, *p_hsth = nullptr, *p_w1th = nullptr, *p_w2th = nullptr;
    cudaGetSymbolAddress(&p_proj, g_proj);
    cudaGetSymbolAddress(&p_yh, g_yh);
    cudaGetSymbolAddress(&p_hsth, g_hsth);
    cudaGetSymbolAddress(&p_w1th, g_w1th);
    cudaGetSymbolAddress(&p_w2th, g_w2th);

    cudaFuncSetAttribute(gemm_f16_kernel, cudaFuncAttributeMaxDynamicSharedMemorySize, GEMM_DSMEM);

    // 0) pre-convert GEMM operands to fp16
    {
        int n4;
        n4 = LSEQ * DMODEL / 4;
        cvt_f16_kernel<<<(n4 + 255) / 256, 256>>>(hs, (__half*)p_hsth, n4);
        n4 = DPROJ * DMODEL / 4;
        cvt_f16_kernel<<<(n4 + 255) / 256, 256>>>(in_proj_w, (__half*)p_w1th, n4);
        n4 = DMODEL * DINTER / 4;
        cvt_f16_kernel<<<(n4 + 255) / 256, 256>>>(out_proj_w, (__half*)p_w2th, n4);
    }

    // 1) in-proj GEMM (fp16, ldmatrix, M-fast raster)
    gemm_f16_kernel<<<dim3(LSEQ / 128, DPROJ / 128), 128, GEMM_DSMEM>>>(
        (const __half*)p_hsth, (const __half*)p_w1th, (float*)p_proj, DPROJ, DMODEL);
    // 2) causal depthwise conv + silu
    conv_silu_kernel<<<(LSEQ * DCONV + 255) / 256, 256>>>(conv_w, conv_b);
    // 3) dt softplus + per-chunk cumsum of A*dt
    dt_scan_kernel<<<dim3(NCH, NH), CSZ>>>(dt_bias, A_log);
    // 4) C·B^T per (chunk, group)
    cb_kernel<<<dim3(NCH, NG), 256>>>();
    // 5) intra-chunk output + D residual
    ydiag_kernel<<<dim3(NCH, NH), 256>>>(Dp);
    // 6) local chunk states
    states_kernel<<<dim3(NCH, NH), 256>>>();
    // 7) inter-chunk state scan
    prefix_kernel<<<(NH * DP * DN + 255) / 256, 256>>>();
    // 8) off-diagonal output
    yoff_kernel<<<dim3(NCH, NH), 256>>>();
    // 9) gated RMSNorm (emits fp16)
    rms_gate_kernel<<<LSEQ, 256>>>(norm_w);
    // 10) out-proj GEMM (fp16, ldmatrix, M-fast raster)
    gemm_f16_kernel<<<dim3(LSEQ / 128, DMODEL / 128), 128, GEMM_DSMEM>>>(
        (const __half*)p_yh, (const __half*)p_w2th, out, DMODEL, DINTER);
}

// round 13
// speedup vs baseline: 1.0491x; 1.0491x over previous
#include <cuda_runtime.h>
#include <cuda_fp16.h>
#include <math.h>
#include <stdint.h>

// ---------------- Problem constants ----------------
#define LSEQ   2048
#define DMODEL 4096
#define NH     128
#define DP     64
#define NG     8
#define DN     128
#define CSZ    128
#define NCH    (LSEQ / CSZ)
#define KCONV  4
#define DINTER 8192
#define DCONV  10240
#define DPROJ  18560
#define RMS_EPS 1e-5f

// ---------------- Scratch ----------------
__device__ float g_proj[LSEQ * DPROJ];
__device__ float g_xbc[LSEQ * DCONV];
__device__ float g_dt[LSEQ * NH];
__device__ float g_acs[NCH * NH * CSZ];
__device__ float g_alast[NCH * NH];
__device__ float g_cbt[NCH * NG * CSZ * CSZ];
__device__ float g_states[NCH * NH * DP * DN];
__device__ float g_prefix[NCH * NH * DP * DN];
__device__ float g_y[LSEQ * DINTER];
// fp16 copies of GEMM operands
__device__ __half g_hsth[LSEQ * DMODEL];
__device__ __half g_w1th[DPROJ * DMODEL];
__device__ __half g_w2th[DMODEL * DINTER];
__device__ __half g_yh[LSEQ * DINTER];

// ---------------- helpers ----------------
__device__ __forceinline__ void mma_f16(float c[4], const uint32_t a[4], const uint32_t b[2]) {
    asm volatile(
        "mma.sync.aligned.m16n8k16.row.col.f32.f16.f16.f32 "
        "{%0,%1,%2,%3}, {%4,%5,%6,%7}, {%8,%9}, {%0,%1,%2,%3};"
        : "+f"(c[0]), "+f"(c[1]), "+f"(c[2]), "+f"(c[3])
        : "r"(a[0]), "r"(a[1]), "r"(a[2]), "r"(a[3]), "r"(b[0]), "r"(b[1]));
}
__device__ __forceinline__ float fast_silu(float x) {
    float t;
    asm("tanh.approx.f32 %0, %1;" : "=f"(t) : "f"(x * 0.5f));
    return 0.5f * x * (1.f + t);
}
__device__ __forceinline__ uint32_t smem_u32(const void* p) {
    uint32_t a;
    asm("{ .reg .u64 t; cvta.to.shared.u64 t, %1; cvt.u32.u64 %0, t; }" : "=r"(a) : "l"(p));
    return a;
}
__device__ __forceinline__ void cp_async16(uint32_t saddr, const void* gaddr) {
    asm volatile("cp.async.cg.shared.global [%0], [%1], 16;" :: "r"(saddr), "l"(gaddr));
}
#define CP_COMMIT() asm volatile("cp.async.commit_group;" ::: "memory")
#define CP_WAIT(n)  asm volatile("cp.async.wait_group %0;" :: "n"(n) : "memory")

// ---------------- fp32 -> fp16 pre-conversion ----------------
__global__ void cvt_f16_kernel(const float* __restrict__ in, __half* __restrict__ out, int n4)
{
    int i = blockIdx.x * blockDim.x + threadIdx.x;
    if (i >= n4) return;
    float4 v = ((const float4*)in)[i];
    __half2 h0 = __floats2half2_rn(v.x, v.y);
    __half2 h1 = __floats2half2_rn(v.z, v.w);
    uint2 o;
    o.x = *(uint32_t*)&h0;
    o.y = *(uint32_t*)&h1;
    ((uint2*)out)[i] = o;
}

// ---------------- fp16 GEMM (R11-proven): scalar frag loads, warp tile 64x64, BK=64, 3 stages ----------------
// C[M,Nd] = A[M,Kd]*B[Nd,Kd]^T. grid.x = M tiles (fast) for L2 reuse of B.
#define GSTAGES 3
#define STAGEW  (128 * 32)
#define GEMM_DSMEM (GSTAGES * 2 * STAGEW * 4)   // 98304 bytes

__global__ __launch_bounds__(128, 2) void gemm_f16_kernel(
    const __half* __restrict__ A, const __half* __restrict__ B, float* __restrict__ C,
    int Nd, int Kd)
{
    extern __shared__ float smf[];
    float* const Abuf = smf;
    float* const Bbuf = smf + GSTAGES * STAGEW;

    const int tid  = threadIdx.x;
    const int lane = tid & 31, warp = tid >> 5;
    const int wm = (warp >> 1) * 64;
    const int wn = (warp & 1) * 64;
    const int g  = lane >> 2, tq = lane & 3;
    const int bm = blockIdx.x * 128, bn = blockIdx.y * 128;   // M fast, N slow

    const int r0 = tid >> 3, c = tid & 7;
    const uint32_t swoff = (uint32_t)((c ^ (r0 & 7)) << 4);
    const __half* AgBase = A + (size_t)(bm + r0) * Kd + c * 8;
    const __half* BgBase = B + (size_t)(bn + r0) * Kd + c * 8;
    const uint32_t sA0 = smem_u32(Abuf) + (uint32_t)(r0 * 128) + swoff;
    const uint32_t sB0 = smem_u32(Bbuf) + (uint32_t)(r0 * 128) + swoff;

    const int KT = Kd >> 6;

#pragma unroll
    for (int s = 0; s < GSTAGES - 1; s++) {
        const uint32_t so = (uint32_t)(s * STAGEW * 4);
        const size_t ko = (size_t)s * 64;
#pragma unroll
        for (int j = 0; j < 8; j++) {
            cp_async16(sA0 + so + j * 16 * 128, AgBase + (size_t)(16 * j) * Kd + ko);
            cp_async16(sB0 + so + j * 16 * 128, BgBase + (size_t)(16 * j) * Kd + ko);
        }
        CP_COMMIT();
    }

    float acc[4][8][4];
#pragma unroll
    for (int mt = 0; mt < 4; mt++)
#pragma unroll
        for (int nt = 0; nt < 8; nt++)
#pragma unroll
            for (int qq = 0; qq < 4; qq++) acc[mt][nt][qq] = 0.f;

    int buf = 0;
    for (int kt = 0; kt < KT; kt++) {
        CP_WAIT(1);
        __syncthreads();

        const int pf = kt + GSTAGES - 1;
        if (pf < KT) {
            const int pb = pf % GSTAGES;
            const uint32_t so = (uint32_t)(pb * STAGEW * 4);
            const size_t ko = (size_t)pf * 64;
#pragma unroll
            for (int j = 0; j < 8; j++) {
                cp_async16(sA0 + so + j * 16 * 128, AgBase + (size_t)(16 * j) * Kd + ko);
                cp_async16(sB0 + so + j * 16 * 128, BgBase + (size_t)(16 * j) * Kd + ko);
            }
        }
        CP_COMMIT();

        const uint32_t* As = (const uint32_t*)(Abuf + buf * STAGEW);
        const uint32_t* Bs = (const uint32_t*)(Bbuf + buf * STAGEW);
#pragma unroll
        for (int ks = 0; ks < 4; ks++) {
            const int kq0 = ((2 * ks)     ^ g) * 4 + tq;
            const int kq1 = ((2 * ks + 1) ^ g) * 4 + tq;
            uint32_t af[4][4], bf[8][2];
#pragma unroll
            for (int mt = 0; mt < 4; mt++) {
                const int m0 = wm + mt * 16;
                af[mt][0] = As[(m0 + g    ) * 32 + kq0];
                af[mt][1] = As[(m0 + g + 8) * 32 + kq0];
                af[mt][2] = As[(m0 + g    ) * 32 + kq1];
                af[mt][3] = As[(m0 + g + 8) * 32 + kq1];
            }
#pragma unroll
            for (int nt = 0; nt < 8; nt++) {
                const int n0 = wn + nt * 8;
                bf[nt][0] = Bs[(n0 + g) * 32 + kq0];
                bf[nt][1] = Bs[(n0 + g) * 32 + kq1];
            }
#pragma unroll
            for (int mt = 0; mt < 4; mt++)
#pragma unroll
                for (int nt = 0; nt < 8; nt++)
                    mma_f16(acc[mt][nt], af[mt], bf[nt]);
        }
        buf = (buf + 1) % GSTAGES;
    }

#pragma unroll
    for (int mt = 0; mt < 4; mt++) {
#pragma unroll
        for (int nt = 0; nt < 8; nt++) {
            const int row = bm + wm + mt * 16 + g;
            const int col = bn + wn + nt * 8 + 2 * tq;
            *(float2*)&C[(size_t)row * Nd + col]       = make_float2(acc[mt][nt][0], acc[mt][nt][1]);
            *(float2*)&C[(size_t)(row + 8) * Nd + col] = make_float2(acc[mt][nt][2], acc[mt][nt][3]);
        }
    }
}

// ---------------- Depthwise causal conv (K=4) + SiLU, 4 channels/thread (float4) ----------------
__global__ void conv_silu_kernel(const float* __restrict__ conv_w, const float* __restrict__ conv_b)
{
    int idx = blockIdx.x * blockDim.x + threadIdx.x;
    if (idx >= LSEQ * (DCONV / 4)) return;
    const int t  = idx / (DCONV / 4);
    const int c4 = idx % (DCONV / 4);          // channel group: channels c4*4 .. c4*4+3
    const int cbase = c4 * 4;

    // per-channel taps: conv_w[c][0][k], 4 contiguous -> one float4 per channel
    float4 w0 = *(const float4*)(conv_w + (size_t)(cbase + 0) * KCONV);
    float4 w1 = *(const float4*)(conv_w + (size_t)(cbase + 1) * KCONV);
    float4 w2 = *(const float4*)(conv_w + (size_t)(cbase + 2) * KCONV);
    float4 w3 = *(const float4*)(conv_w + (size_t)(cbase + 3) * KCONV);
    float4 acc = *(const float4*)(conv_b + cbase);

    const float wk[4][4] = {{w0.x, w0.y, w0.z, w0.w},
                            {w1.x, w1.y, w1.z, w1.w},
                            {w2.x, w2.y, w2.z, w2.w},
                            {w3.x, w3.y, w3.z, w3.w}};
    float a[4] = {acc.x, acc.y, acc.z, acc.w};
#pragma unroll
    for (int k = 0; k < KCONV; k++) {
        int tt = t + k - (KCONV - 1);
        if (tt >= 0) {
            float4 p = *(const float4*)(g_proj + (size_t)tt * DPROJ + DINTER + cbase);
            a[0] += wk[0][k] * p.x;
            a[1] += wk[1][k] * p.y;
            a[2] += wk[2][k] * p.z;
            a[3] += wk[3][k] * p.w;
        }
    }
    float4 o = make_float4(fast_silu(a[0]), fast_silu(a[1]), fast_silu(a[2]), fast_silu(a[3]));
    *(float4*)(g_xbc + (size_t)t * DCONV + cbase) = o;
}

// ---------------- dt softplus + per-chunk cumsum of A*dt ----------------
__global__ __launch_bounds__(CSZ) void dt_scan_kernel(
    const float* __restrict__ dt_bias, const float* __restrict__ A_log)
{
    int c = blockIdx.x, h = blockIdx.y, l = threadIdx.x;
    int t = c * CSZ + l;
    float raw = g_proj[(size_t)t * DPROJ + DINTER + DCONV + h] + dt_bias[h];
    float dtp = (raw > 0.f) ? (raw + log1pf(__expf(-raw))) : log1pf(__expf(raw));
    g_dt[t * NH + h] = dtp;
    float a = -__expf(A_log[h]) * dtp;

    __shared__ float s[CSZ];
    s[l] = a;
    __syncthreads();
#pragma unroll
    for (int off = 1; off < CSZ; off <<= 1) {
        float v = (l >= off) ? s[l - off] : 0.f;
        __syncthreads();
        s[l] += v;
        __syncthreads();
    }
    g_acs[(c * NH + h) * CSZ + l] = s[l];
    if (l == CSZ - 1) g_alast[c * NH + h] = s[l];
}

// ---------------- CBt[c][g][s][l] = sum_n C[l,n]*B[s,n] ----------------
__global__ __launch_bounds__(256) void cb_kernel()
{
    int c = blockIdx.x, g = blockIdx.y;
    int tid = threadIdx.x, tx = tid & 15, ty = tid >> 4;
    __shared__ float Csn[16][CSZ];
    __shared__ float Bsn[16][CSZ];
    float acc[8][8];
#pragma unroll
    for (int i = 0; i < 8; i++)
#pragma unroll
        for (int j = 0; j < 8; j++) acc[i][j] = 0.f;

    const float* Cg = g_xbc + DINTER + NG * DN + g * DN;
    const float* Bg = g_xbc + DINTER + g * DN;

    for (int n0 = 0; n0 < DN; n0 += 16) {
        for (int i = tid; i < CSZ * 4; i += 256) {
            int r = i >> 2, q = i & 3;
            const size_t row = (size_t)(c * CSZ + r) * DCONV + n0 + q * 4;
            float4 cv = *(const float4*)(Cg + row);
            float4 bv = *(const float4*)(Bg + row);
            Csn[q * 4 + 0][r] = cv.x; Csn[q * 4 + 1][r] = cv.y;
            Csn[q * 4 + 2][r] = cv.z; Csn[q * 4 + 3][r] = cv.w;
            Bsn[q * 4 + 0][r] = bv.x; Bsn[q * 4 + 1][r] = bv.y;
            Bsn[q * 4 + 2][r] = bv.z; Bsn[q * 4 + 3][r] = bv.w;
        }
        __syncthreads();
#pragma unroll
        for (int nn = 0; nn < 16; nn++) {
            float4 c0 = *(const float4*)&Csn[nn][tx * 8];
            float4 c1 = *(const float4*)&Csn[nn][tx * 8 + 4];
            float4 b0 = *(const float4*)&Bsn[nn][ty * 8];
            float4 b1 = *(const float4*)&Bsn[nn][ty * 8 + 4];
            float cl[8] = {c0.x, c0.y, c0.z, c0.w, c1.x, c1.y, c1.z, c1.w};
            float bs[8] = {b0.x, b0.y, b0.z, b0.w, b1.x, b1.y, b1.z, b1.w};
#pragma unroll
            for (int si = 0; si < 8; si++)
#pragma unroll
                for (int li = 0; li < 8; li++) acc[si][li] += cl[li] * bs[si];
        }
        __syncthreads();
    }
    float* out = g_cbt + (size_t)(c * NG + g) * CSZ * CSZ;
#pragma unroll
    for (int si = 0; si < 8; si++) {
        int s = ty * 8 + si;
        *(float4*)(out + (size_t)s * CSZ + tx * 8)     = make_float4(acc[si][0], acc[si][1], acc[si][2], acc[si][3]);
        *(float4*)(out + (size_t)s * CSZ + tx * 8 + 4) = make_float4(acc[si][4], acc[si][5], acc[si][6], acc[si][7]);
    }
}

// ---------------- Y_diag + D residual (factorized decay exps) ----------------
__global__ __launch_bounds__(256) void ydiag_kernel(const float* __restrict__ Dparam)
{
    int c = blockIdx.x, h = blockIdx.y, g = h >> 4;
    int tid = threadIdx.x, tx = tid & 15, ty = tid >> 4;
    __shared__ float xs[CSZ][DP];
    __shared__ float Ms[CSZ][17];
    __shared__ float acsS[CSZ];
    __shared__ float dts[CSZ];
    __shared__ float el[CSZ];
    __shared__ float esd[16];

    for (int i = tid; i < CSZ * DP / 4; i += 256) {
        int r = i >> 4, q = i & 15;
        *(float4*)&xs[r][q * 4] =
            *(const float4*)(g_xbc + (size_t)(c * CSZ + r) * DCONV + h * DP + q * 4);
    }
    if (tid < CSZ) {
        dts[tid]  = g_dt[(c * CSZ + tid) * NH + h];
        acsS[tid] = g_acs[(c * NH + h) * CSZ + tid];
    }
    __syncthreads();

    float acc[8][4];
#pragma unroll
    for (int i = 0; i < 8; i++)
#pragma unroll
        for (int j = 0; j < 4; j++) acc[i][j] = 0.f;

    const float* cbBase = g_cbt + (size_t)(c * NG + g) * CSZ * CSZ;
    const int ss_row = tid >> 4;
    const int lg     = tid & 15;

    for (int s0 = 0; s0 < CSZ; s0 += 16) {
        const float a0 = acsS[s0];
        if (tid < CSZ) el[tid] = __expf(acsS[tid] - a0);
        else if (tid < CSZ + 16) {
            int s = s0 + (tid - CSZ);
            esd[tid - CSZ] = __expf(a0 - acsS[s]) * dts[s];
        }
        __syncthreads();

        {
            const int s = s0 + ss_row;
            const float fs = esd[ss_row];
            const float* cbRow = cbBase + (size_t)s * CSZ;
#pragma unroll
            for (int k = 0; k < 8; k++) {
                const int l = lg * 8 + k;
                Ms[l][ss_row] = (s <= l) ? cbRow[l] * el[l] * fs : 0.f;
            }
        }
        __syncthreads();

#pragma unroll
        for (int ss = 0; ss < 16; ss++) {
            const int s = s0 + ss;
            float msv[8];
#pragma unroll
            for (int i = 0; i < 8; i++) msv[i] = Ms[ty * 8 + i][ss];
            float4 xv4 = *(const float4*)&xs[s][tx * 4];
#pragma unroll
            for (int i = 0; i < 8; i++) {
                acc[i][0] += msv[i] * xv4.x;
                acc[i][1] += msv[i] * xv4.y;
                acc[i][2] += msv[i] * xv4.z;
                acc[i][3] += msv[i] * xv4.w;
            }
        }
        __syncthreads();
    }

    const float dcoef = Dparam[h];
#pragma unroll
    for (int i = 0; i < 8; i++) {
        int l = ty * 8 + i;
        float4 xr = *(const float4*)&xs[l][tx * 4];
        float4 o = make_float4(acc[i][0] + dcoef * xr.x, acc[i][1] + dcoef * xr.y,
                               acc[i][2] + dcoef * xr.z, acc[i][3] + dcoef * xr.w);
        *(float4*)(g_y + (size_t)(c * CSZ + l) * DINTER + h * DP + tx * 4) = o;
    }
}

// ---------------- Local chunk states ----------------
__global__ __launch_bounds__(256) void states_kernel()
{
    int c = blockIdx.x, h = blockIdx.y, g = h >> 4;
    int tid = threadIdx.x, tx = tid & 15, ty = tid >> 4;
    __shared__ float Bsh[32][DN];
    __shared__ float xds[32][DP];
    __shared__ float dec[32];
    float acc[4][8];
#pragma unroll
    for (int i = 0; i < 4; i++)
#pragma unroll
        for (int j = 0; j < 8; j++) acc[i][j] = 0.f;

    const float al = g_alast[c * NH + h];
    for (int l0 = 0; l0 < CSZ; l0 += 32) {
        for (int i = tid; i < 32 * DN / 4; i += 256) {
            int r = i >> 5, q = i & 31;
            *(float4*)&Bsh[r][q * 4] = *(const float4*)(
                g_xbc + (size_t)(c * CSZ + l0 + r) * DCONV + DINTER + g * DN + q * 4);
        }
        for (int i = tid; i < 32 * DP / 4; i += 256) {
            int r = i >> 4, q = i & 15;
            int t = c * CSZ + l0 + r;
            float4 xv = *(const float4*)(g_xbc + (size_t)t * DCONV + h * DP + q * 4);
            float d = g_dt[t * NH + h];
            xv.x *= d; xv.y *= d; xv.z *= d; xv.w *= d;
            *(float4*)&xds[r][q * 4] = xv;
        }
        if (tid < 32) dec[tid] = __expf(al - g_acs[(c * NH + h) * CSZ + l0 + tid]);
        __syncthreads();
#pragma unroll 8
        for (int ll = 0; ll < 32; ll++) {
            float d = dec[ll];
            float4 b0 = *(const float4*)&Bsh[ll][tx * 8];
            float4 b1 = *(const float4*)&Bsh[ll][tx * 8 + 4];
            float bb[8] = {b0.x, b0.y, b0.z, b0.w, b1.x, b1.y, b1.z, b1.w};
            float4 xv = *(const float4*)&xds[ll][ty * 4];
            float xp[4] = {xv.x * d, xv.y * d, xv.z * d, xv.w * d};
#pragma unroll
            for (int pi = 0; pi < 4; pi++)
#pragma unroll
                for (int nj = 0; nj < 8; nj++) acc[pi][nj] += xp[pi] * bb[nj];
        }
        __syncthreads();
    }
    float* out = g_states + (size_t)(c * NH + h) * DP * DN;
#pragma unroll
    for (int pi = 0; pi < 4; pi++) {
        int p = ty * 4 + pi;
        *(float4*)(out + (size_t)p * DN + tx * 8)     = make_float4(acc[pi][0], acc[pi][1], acc[pi][2], acc[pi][3]);
        *(float4*)(out + (size_t)p * DN + tx * 8 + 4) = make_float4(acc[pi][4], acc[pi][5], acc[pi][6], acc[pi][7]);
    }
}

// ---------------- Inter-chunk scan ----------------
__global__ void prefix_kernel()
{
    int idx = blockIdx.x * blockDim.x + threadIdx.x;
    if (idx >= NH * DP * DN) return;
    int h = idx >> 13;
    float s = 0.f;
#pragma unroll
    for (int c = 0; c < NCH; c++) {
        size_t off = (size_t)c * NH * DP * DN + idx;
        g_prefix[off] = s;
        s = __expf(g_alast[c * NH + h]) * s + g_states[off];
    }
}

// ---------------- Y_off ----------------
__global__ __launch_bounds__(256) void yoff_kernel()
{
    int c = blockIdx.x, h = blockIdx.y, g = h >> 4;
    int tid = threadIdx.x, tx = tid & 15, ty = tid >> 4;
    __shared__ float Cs[CSZ][32];
    __shared__ float Pf[DP][33];
    __shared__ float acsS[CSZ];
    if (tid < CSZ) acsS[tid] = g_acs[(c * NH + h) * CSZ + tid];

    float acc[8][4];
#pragma unroll
    for (int i = 0; i < 8; i++)
#pragma unroll
        for (int j = 0; j < 4; j++) acc[i][j] = 0.f;

    for (int n0 = 0; n0 < DN; n0 += 32) {
        for (int i = tid; i < CSZ * 8; i += 256) {
            int r = i >> 3, q = i & 7;
            *(float4*)&Cs[r][q * 4] = *(const float4*)(
                g_xbc + (size_t)(c * CSZ + r) * DCONV + DINTER + NG * DN + g * DN + n0 + q * 4);
        }
        for (int i = tid; i < DP * 8; i += 256) {
            int r = i >> 3, q = i & 7;
            float4 v = *(const float4*)(
                g_prefix + ((size_t)(c * NH + h) * DP + r) * DN + n0 + q * 4);
            Pf[r][q * 4 + 0] = v.x; Pf[r][q * 4 + 1] = v.y;
            Pf[r][q * 4 + 2] = v.z; Pf[r][q * 4 + 3] = v.w;
        }
        __syncthreads();
#pragma unroll 8
        for (int nn = 0; nn < 32; nn++) {
            float cl[8], pv[4];
#pragma unroll
            for (int i = 0; i < 8; i++) cl[i] = Cs[ty * 8 + i][nn];
#pragma unroll
            for (int j = 0; j < 4; j++) pv[j] = Pf[tx * 4 + j][nn];
#pragma unroll
            for (int i = 0; i < 8; i++)
#pragma unroll
                for (int j = 0; j < 4; j++) acc[i][j] += cl[i] * pv[j];
        }
        __syncthreads();
    }
#pragma unroll
    for (int i = 0; i < 8; i++) {
        int l = ty * 8 + i;
        float e = __expf(acsS[l]);
        float* yp = g_y + (size_t)(c * CSZ + l) * DINTER + h * DP + tx * 4;
        float4 y = *(float4*)yp;
        y.x += e * acc[i][0]; y.y += e * acc[i][1];
        y.z += e * acc[i][2]; y.w += e * acc[i][3];
        *(float4*)yp = y;
    }
}

// ---------------- RMSNorm * norm_w * silu(gate); float4, emits fp16 for GEMM2 ----------------
__global__ __launch_bounds__(256) void rms_gate_kernel(const float* __restrict__ norm_w)
{
    int t = blockIdx.x, tid = threadIdx.x;
    const size_t base = (size_t)t * DINTER;
    float ss = 0.f;
    for (int i = tid; i < DINTER / 4; i += 256) {
        float4 v = *(const float4*)(g_y + base + i * 4);
        ss += v.x * v.x + v.y * v.y + v.z * v.z + v.w * v.w;
    }
    __shared__ float red[256];
    red[tid] = ss;
    __syncthreads();
#pragma unroll
    for (int o = 128; o > 0; o >>= 1) {
        if (tid < o) red[tid] += red[tid + o];
        __syncthreads();
    }
    float inv = rsqrtf(red[0] / (float)DINTER + RMS_EPS);
    for (int i = tid; i < DINTER / 4; i += 256) {
        float4 v = *(const float4*)(g_y + base + i * 4);
        float4 w = *(const float4*)(norm_w + i * 4);
        float4 gt = *(const float4*)(g_proj + (size_t)t * DPROJ + i * 4);
        float r0 = v.x * inv * w.x * fast_silu(gt.x);
        float r1 = v.y * inv * w.y * fast_silu(gt.y);
        float r2 = v.z * inv * w.z * fast_silu(gt.z);
        float r3 = v.w * inv * w.w * fast_silu(gt.w);
        __half2 h0 = __floats2half2_rn(r0, r1);
        __half2 h1 = __floats2half2_rn(r2, r3);
        uint2 o;
        o.x = *(uint32_t*)&h0;
        o.y = *(uint32_t*)&h1;
        *(uint2*)(g_yh + base + i * 4) = o;
    }
}

// ---------------- Launch ----------------
extern "C" void kernel_launch(void* const* d_in, const int* in_sizes, int n_in,
                              void* d_out, int out_size)
{
    (void)in_sizes; (void)n_in; (void)out_size;
    const float* hs         = (const float*)d_in[0];
    const float* in_proj_w  = (const float*)d_in[1];
    const float* conv_w     = (const float*)d_in[2];
    const float* conv_b     = (const float*)d_in[3];
    const float* dt_bias    = (const float*)d_in[4];
    const float* A_log      = (const float*)d_in[5];
    const float* Dp         = (const float*)d_in[6];
    const float* norm_w     = (const float*)d_in[7];
    const float* out_proj_w = (const float*)d_in[8];
    float* out = (float*)d_out;

    void *p_proj = nullptr, *p_yh = nullptr, *p_hsth = nullptr, *p_w1th = nullptr, *p_w2th = nullptr;
    cudaGetSymbolAddress(&p_proj, g_proj);
    cudaGetSymbolAddress(&p_yh, g_yh);
    cudaGetSymbolAddress(&p_hsth, g_hsth);
    cudaGetSymbolAddress(&p_w1th, g_w1th);
    cudaGetSymbolAddress(&p_w2th, g_w2th);

    cudaFuncSetAttribute(gemm_f16_kernel, cudaFuncAttributeMaxDynamicSharedMemorySize, GEMM_DSMEM);

    // 0) pre-convert GEMM operands to fp16
    {
        int n4;
        n4 = LSEQ * DMODEL / 4;
        cvt_f16_kernel<<<(n4 + 255) / 256, 256>>>(hs, (__half*)p_hsth, n4);
        n4 = DPROJ * DMODEL / 4;
        cvt_f16_kernel<<<(n4 + 255) / 256, 256>>>(in_proj_w, (__half*)p_w1th, n4);
        n4 = DMODEL * DINTER / 4;
        cvt_f16_kernel<<<(n4 + 255) / 256, 256>>>(out_proj_w, (__half*)p_w2th, n4);
    }

    // 1) in-proj GEMM (fp16, M-fast raster)
    gemm_f16_kernel<<<dim3(LSEQ / 128, DPROJ / 128), 128, GEMM_DSMEM>>>(
        (const __half*)p_hsth, (const __half*)p_w1th, (float*)p_proj, DPROJ, DMODEL);
    // 2) causal depthwise conv + silu (4 channels/thread)
    conv_silu_kernel<<<(LSEQ * (DCONV / 4) + 255) / 256, 256>>>(conv_w, conv_b);
    // 3) dt softplus + per-chunk cumsum of A*dt
    dt_scan_kernel<<<dim3(NCH, NH), CSZ>>>(dt_bias, A_log);
    // 4) C·B^T per (chunk, group)
    cb_kernel<<<dim3(NCH, NG), 256>>>();
    // 5) intra-chunk output + D residual
    ydiag_kernel<<<dim3(NCH, NH), 256>>>(Dp);
    // 6) local chunk states
    states_kernel<<<dim3(NCH, NH), 256>>>();
    // 7) inter-chunk state scan
    prefix_kernel<<<(NH * DP * DN + 255) / 256, 256>>>();
    // 8) off-diagonal output
    yoff_kernel<<<dim3(NCH, NH), 256>>>();
    // 9) gated RMSNorm (float4, emits fp16)
    rms_gate_kernel<<<LSEQ, 256>>>(norm_w);
    // 10) out-proj GEMM (fp16, M-fast raster)
    gemm_f16_kernel<<<dim3(LSEQ / 128, DMODEL / 128), 128, GEMM_DSMEM>>>(
        (const __half*)p_yh, (const __half*)p_w2th, out, DMODEL, DINTER);
}

// round 14
// speedup vs baseline: 1.0556x; 1.0062x over previous
#include <cuda_runtime.h>
#include <cuda_fp16.h>
#include <math.h>
#include <stdint.h>

// ---------------- Problem constants ----------------
#define LSEQ   2048
#define DMODEL 4096
#define NH     128
#define DP     64
#define NG     8
#define DN     128
#define CSZ    128
#define NCH    (LSEQ / CSZ)
#define KCONV  4
#define DINTER 8192
#define DCONV  10240
#define DPROJ  18560
#define RMS_EPS 1e-5f

// ---------------- Scratch ----------------
__device__ float g_proj[LSEQ * DPROJ];
__device__ float g_xbc[LSEQ * DCONV];
__device__ float g_dt[LSEQ * NH];
__device__ float g_acs[NCH * NH * CSZ];
__device__ float g_alast[NCH * NH];
__device__ float g_cbt[NCH * NG * CSZ * CSZ];
__device__ float g_states[NCH * NH * DP * DN];
__device__ float g_prefix[NCH * NH * DP * DN];
__device__ float g_y[LSEQ * DINTER];
// fp16 copies of GEMM operands
__device__ __half g_hsth[LSEQ * DMODEL];
__device__ __half g_w1th[DPROJ * DMODEL];
__device__ __half g_w2th[DMODEL * DINTER];
__device__ __half g_yh[LSEQ * DINTER];

// ---------------- helpers ----------------
__device__ __forceinline__ void mma_f16(float c[4], const uint32_t a[4], const uint32_t b[2]) {
    asm volatile(
        "mma.sync.aligned.m16n8k16.row.col.f32.f16.f16.f32 "
        "{%0,%1,%2,%3}, {%4,%5,%6,%7}, {%8,%9}, {%0,%1,%2,%3};"
        : "+f"(c[0]), "+f"(c[1]), "+f"(c[2]), "+f"(c[3])
        : "r"(a[0]), "r"(a[1]), "r"(a[2]), "r"(a[3]), "r"(b[0]), "r"(b[1]));
}
__device__ __forceinline__ float fast_silu(float x) {
    float t;
    asm("tanh.approx.f32 %0, %1;" : "=f"(t) : "f"(x * 0.5f));
    return 0.5f * x * (1.f + t);
}
__device__ __forceinline__ uint32_t smem_u32(const void* p) {
    uint32_t a;
    asm("{ .reg .u64 t; cvta.to.shared.u64 t, %1; cvt.u32.u64 %0, t; }" : "=r"(a) : "l"(p));
    return a;
}
__device__ __forceinline__ void cp_async16(uint32_t saddr, const void* gaddr) {
    asm volatile("cp.async.cg.shared.global [%0], [%1], 16;" :: "r"(saddr), "l"(gaddr));
}
#define CP_COMMIT() asm volatile("cp.async.commit_group;" ::: "memory")
#define CP_WAIT(n)  asm volatile("cp.async.wait_group %0;" :: "n"(n) : "memory")

// ---------------- fp32 -> fp16 pre-conversion ----------------
__global__ void cvt_f16_kernel(const float* __restrict__ in, __half* __restrict__ out, int n4)
{
    int i = blockIdx.x * blockDim.x + threadIdx.x;
    if (i >= n4) return;
    float4 v = ((const float4*)in)[i];
    __half2 h0 = __floats2half2_rn(v.x, v.y);
    __half2 h1 = __floats2half2_rn(v.z, v.w);
    uint2 o;
    o.x = *(uint32_t*)&h0;
    o.y = *(uint32_t*)&h1;
    ((uint2*)out)[i] = o;
}

// ---------------- fp16 GEMM (R11-proven): scalar frag loads, warp tile 64x64, BK=64, 3 stages ----------------
#define GSTAGES 3
#define STAGEW  (128 * 32)
#define GEMM_DSMEM (GSTAGES * 2 * STAGEW * 4)   // 98304 bytes

__global__ __launch_bounds__(128, 2) void gemm_f16_kernel(
    const __half* __restrict__ A, const __half* __restrict__ B, float* __restrict__ C,
    int Nd, int Kd)
{
    extern __shared__ float smf[];
    float* const Abuf = smf;
    float* const Bbuf = smf + GSTAGES * STAGEW;

    const int tid  = threadIdx.x;
    const int lane = tid & 31, warp = tid >> 5;
    const int wm = (warp >> 1) * 64;
    const int wn = (warp & 1) * 64;
    const int g  = lane >> 2, tq = lane & 3;
    const int bm = blockIdx.x * 128, bn = blockIdx.y * 128;   // M fast, N slow

    const int r0 = tid >> 3, c = tid & 7;
    const uint32_t swoff = (uint32_t)((c ^ (r0 & 7)) << 4);
    const __half* AgBase = A + (size_t)(bm + r0) * Kd + c * 8;
    const __half* BgBase = B + (size_t)(bn + r0) * Kd + c * 8;
    const uint32_t sA0 = smem_u32(Abuf) + (uint32_t)(r0 * 128) + swoff;
    const uint32_t sB0 = smem_u32(Bbuf) + (uint32_t)(r0 * 128) + swoff;

    const int KT = Kd >> 6;

#pragma unroll
    for (int s = 0; s < GSTAGES - 1; s++) {
        const uint32_t so = (uint32_t)(s * STAGEW * 4);
        const size_t ko = (size_t)s * 64;
#pragma unroll
        for (int j = 0; j < 8; j++) {
            cp_async16(sA0 + so + j * 16 * 128, AgBase + (size_t)(16 * j) * Kd + ko);
            cp_async16(sB0 + so + j * 16 * 128, BgBase + (size_t)(16 * j) * Kd + ko);
        }
        CP_COMMIT();
    }

    float acc[4][8][4];
#pragma unroll
    for (int mt = 0; mt < 4; mt++)
#pragma unroll
        for (int nt = 0; nt < 8; nt++)
#pragma unroll
            for (int qq = 0; qq < 4; qq++) acc[mt][nt][qq] = 0.f;

    int buf = 0;
    for (int kt = 0; kt < KT; kt++) {
        CP_WAIT(1);
        __syncthreads();

        const int pf = kt + GSTAGES - 1;
        if (pf < KT) {
            const int pb = pf % GSTAGES;
            const uint32_t so = (uint32_t)(pb * STAGEW * 4);
            const size_t ko = (size_t)pf * 64;
#pragma unroll
            for (int j = 0; j < 8; j++) {
                cp_async16(sA0 + so + j * 16 * 128, AgBase + (size_t)(16 * j) * Kd + ko);
                cp_async16(sB0 + so + j * 16 * 128, BgBase + (size_t)(16 * j) * Kd + ko);
            }
        }
        CP_COMMIT();

        const uint32_t* As = (const uint32_t*)(Abuf + buf * STAGEW);
        const uint32_t* Bs = (const uint32_t*)(Bbuf + buf * STAGEW);
#pragma unroll
        for (int ks = 0; ks < 4; ks++) {
            const int kq0 = ((2 * ks)     ^ g) * 4 + tq;
            const int kq1 = ((2 * ks + 1) ^ g) * 4 + tq;
            uint32_t af[4][4], bf[8][2];
#pragma unroll
            for (int mt = 0; mt < 4; mt++) {
                const int m0 = wm + mt * 16;
                af[mt][0] = As[(m0 + g    ) * 32 + kq0];
                af[mt][1] = As[(m0 + g + 8) * 32 + kq0];
                af[mt][2] = As[(m0 + g    ) * 32 + kq1];
                af[mt][3] = As[(m0 + g + 8) * 32 + kq1];
            }
#pragma unroll
            for (int nt = 0; nt < 8; nt++) {
                const int n0 = wn + nt * 8;
                bf[nt][0] = Bs[(n0 + g) * 32 + kq0];
                bf[nt][1] = Bs[(n0 + g) * 32 + kq1];
            }
#pragma unroll
            for (int mt = 0; mt < 4; mt++)
#pragma unroll
                for (int nt = 0; nt < 8; nt++)
                    mma_f16(acc[mt][nt], af[mt], bf[nt]);
        }
        buf = (buf + 1) % GSTAGES;
    }

#pragma unroll
    for (int mt = 0; mt < 4; mt++) {
#pragma unroll
        for (int nt = 0; nt < 8; nt++) {
            const int row = bm + wm + mt * 16 + g;
            const int col = bn + wn + nt * 8 + 2 * tq;
            *(float2*)&C[(size_t)row * Nd + col]       = make_float2(acc[mt][nt][0], acc[mt][nt][1]);
            *(float2*)&C[(size_t)(row + 8) * Nd + col] = make_float2(acc[mt][nt][2], acc[mt][nt][3]);
        }
    }
}

// ---------------- Depthwise causal conv (K=4) + SiLU, 4 channels/thread ----------------
__global__ void conv_silu_kernel(const float* __restrict__ conv_w, const float* __restrict__ conv_b)
{
    int idx = blockIdx.x * blockDim.x + threadIdx.x;
    if (idx >= LSEQ * (DCONV / 4)) return;
    const int t  = idx / (DCONV / 4);
    const int cbase = (idx % (DCONV / 4)) * 4;

    float4 w0 = *(const float4*)(conv_w + (size_t)(cbase + 0) * KCONV);
    float4 w1 = *(const float4*)(conv_w + (size_t)(cbase + 1) * KCONV);
    float4 w2 = *(const float4*)(conv_w + (size_t)(cbase + 2) * KCONV);
    float4 w3 = *(const float4*)(conv_w + (size_t)(cbase + 3) * KCONV);
    float4 bb = *(const float4*)(conv_b + cbase);

    const float wk[4][4] = {{w0.x, w0.y, w0.z, w0.w},
                            {w1.x, w1.y, w1.z, w1.w},
                            {w2.x, w2.y, w2.z, w2.w},
                            {w3.x, w3.y, w3.z, w3.w}};
    float a[4] = {bb.x, bb.y, bb.z, bb.w};
#pragma unroll
    for (int k = 0; k < KCONV; k++) {
        int tt = t + k - (KCONV - 1);
        if (tt >= 0) {
            float4 p = *(const float4*)(g_proj + (size_t)tt * DPROJ + DINTER + cbase);
            a[0] += wk[0][k] * p.x;
            a[1] += wk[1][k] * p.y;
            a[2] += wk[2][k] * p.z;
            a[3] += wk[3][k] * p.w;
        }
    }
    float4 o = make_float4(fast_silu(a[0]), fast_silu(a[1]), fast_silu(a[2]), fast_silu(a[3]));
    *(float4*)(g_xbc + (size_t)t * DCONV + cbase) = o;
}

// ---------------- dt softplus + per-chunk cumsum of A*dt ----------------
__global__ __launch_bounds__(CSZ) void dt_scan_kernel(
    const float* __restrict__ dt_bias, const float* __restrict__ A_log)
{
    int c = blockIdx.x, h = blockIdx.y, l = threadIdx.x;
    int t = c * CSZ + l;
    float raw = g_proj[(size_t)t * DPROJ + DINTER + DCONV + h] + dt_bias[h];
    float dtp = (raw > 0.f) ? (raw + log1pf(__expf(-raw))) : log1pf(__expf(raw));
    g_dt[t * NH + h] = dtp;
    float a = -__expf(A_log[h]) * dtp;

    __shared__ float s[CSZ];
    s[l] = a;
    __syncthreads();
#pragma unroll
    for (int off = 1; off < CSZ; off <<= 1) {
        float v = (l >= off) ? s[l - off] : 0.f;
        __syncthreads();
        s[l] += v;
        __syncthreads();
    }
    g_acs[(c * NH + h) * CSZ + l] = s[l];
    if (l == CSZ - 1) g_alast[c * NH + h] = s[l];
}

// ---------------- CBt[c][g][s][l] = sum_n C[l,n]*B[s,n] ----------------
__global__ __launch_bounds__(256) void cb_kernel()
{
    int c = blockIdx.x, g = blockIdx.y;
    int tid = threadIdx.x, tx = tid & 15, ty = tid >> 4;
    __shared__ float Csn[16][CSZ];
    __shared__ float Bsn[16][CSZ];
    float acc[8][8];
#pragma unroll
    for (int i = 0; i < 8; i++)
#pragma unroll
        for (int j = 0; j < 8; j++) acc[i][j] = 0.f;

    const float* Cg = g_xbc + DINTER + NG * DN + g * DN;
    const float* Bg = g_xbc + DINTER + g * DN;

    for (int n0 = 0; n0 < DN; n0 += 16) {
        for (int i = tid; i < CSZ * 4; i += 256) {
            int r = i >> 2, q = i & 3;
            const size_t row = (size_t)(c * CSZ + r) * DCONV + n0 + q * 4;
            float4 cv = *(const float4*)(Cg + row);
            float4 bv = *(const float4*)(Bg + row);
            Csn[q * 4 + 0][r] = cv.x; Csn[q * 4 + 1][r] = cv.y;
            Csn[q * 4 + 2][r] = cv.z; Csn[q * 4 + 3][r] = cv.w;
            Bsn[q * 4 + 0][r] = bv.x; Bsn[q * 4 + 1][r] = bv.y;
            Bsn[q * 4 + 2][r] = bv.z; Bsn[q * 4 + 3][r] = bv.w;
        }
        __syncthreads();
#pragma unroll
        for (int nn = 0; nn < 16; nn++) {
            float4 c0 = *(const float4*)&Csn[nn][tx * 8];
            float4 c1 = *(const float4*)&Csn[nn][tx * 8 + 4];
            float4 b0 = *(const float4*)&Bsn[nn][ty * 8];
            float4 b1 = *(const float4*)&Bsn[nn][ty * 8 + 4];
            float cl[8] = {c0.x, c0.y, c0.z, c0.w, c1.x, c1.y, c1.z, c1.w};
            float bs[8] = {b0.x, b0.y, b0.z, b0.w, b1.x, b1.y, b1.z, b1.w};
#pragma unroll
            for (int si = 0; si < 8; si++)
#pragma unroll
                for (int li = 0; li < 8; li++) acc[si][li] += cl[li] * bs[si];
        }
        __syncthreads();
    }
    float* out = g_cbt + (size_t)(c * NG + g) * CSZ * CSZ;
#pragma unroll
    for (int si = 0; si < 8; si++) {
        int s = ty * 8 + si;
        *(float4*)(out + (size_t)s * CSZ + tx * 8)     = make_float4(acc[si][0], acc[si][1], acc[si][2], acc[si][3]);
        *(float4*)(out + (size_t)s * CSZ + tx * 8 + 4) = make_float4(acc[si][4], acc[si][5], acc[si][6], acc[si][7]);
    }
}

// ---------------- FUSED Y_diag + states: one CTA per (chunk, head) ----------------
// Shares the x tile, dt, acs in smem between both computations.
// Dynamic smem layout (floats):
//   xs   [128*64]  @ 0
//   dts  [128]     @ 8192
//   acsS [128]     @ 8320
//   el   [128]     @ 8448
//   esd  [16]      @ 8576
//   work [4128]    @ 8592   (phase A: Ms[128][17]; phase B: Bsh[32][128] + dec[32])
#define YDST_SMEM ((8592 + 4128) * 4)   // 50880 bytes

__global__ __launch_bounds__(256) void ydiag_states_kernel(const float* __restrict__ Dparam)
{
    extern __shared__ float sm[];
    float* const xs   = sm;
    float* const dts  = sm + 8192;
    float* const acsS = sm + 8320;
    float* const el   = sm + 8448;
    float* const esd  = sm + 8576;
    float* const work = sm + 8592;

    int c = blockIdx.x, h = blockIdx.y, g = h >> 4;
    int tid = threadIdx.x, tx = tid & 15, ty = tid >> 4;

    for (int i = tid; i < CSZ * DP / 4; i += 256) {
        int r = i >> 4, q = i & 15;
        *(float4*)(xs + r * DP + q * 4) =
            *(const float4*)(g_xbc + (size_t)(c * CSZ + r) * DCONV + h * DP + q * 4);
    }
    if (tid < CSZ) {
        dts[tid]  = g_dt[(c * CSZ + tid) * NH + h];
        acsS[tid] = g_acs[(c * NH + h) * CSZ + tid];
    }
    __syncthreads();

    // ---- Phase A: Y_diag (l = ty*8+i, p = tx*4+j) ----
    {
        float acc[8][4];
#pragma unroll
        for (int i = 0; i < 8; i++)
#pragma unroll
            for (int j = 0; j < 4; j++) acc[i][j] = 0.f;

        const float* cbBase = g_cbt + (size_t)(c * NG + g) * CSZ * CSZ;
        const int ss_row = tid >> 4;
        const int lg     = tid & 15;

        for (int s0 = 0; s0 < CSZ; s0 += 16) {
            const float a0 = acsS[s0];
            if (tid < CSZ) el[tid] = __expf(acsS[tid] - a0);
            else if (tid < CSZ + 16) {
                int s = s0 + (tid - CSZ);
                esd[tid - CSZ] = __expf(a0 - acsS[s]) * dts[s];
            }
            __syncthreads();

            {
                const int s = s0 + ss_row;
                const float fs = esd[ss_row];
                const float* cbRow = cbBase + (size_t)s * CSZ;
#pragma unroll
                for (int k = 0; k < 8; k++) {
                    const int l = lg * 8 + k;
                    work[l * 17 + ss_row] = (s <= l) ? cbRow[l] * el[l] * fs : 0.f;
                }
            }
            __syncthreads();

#pragma unroll
            for (int ss = 0; ss < 16; ss++) {
                const int s = s0 + ss;
                float msv[8];
#pragma unroll
                for (int i = 0; i < 8; i++) msv[i] = work[(ty * 8 + i) * 17 + ss];
                float4 xv4 = *(const float4*)(xs + s * DP + tx * 4);
#pragma unroll
                for (int i = 0; i < 8; i++) {
                    acc[i][0] += msv[i] * xv4.x;
                    acc[i][1] += msv[i] * xv4.y;
                    acc[i][2] += msv[i] * xv4.z;
                    acc[i][3] += msv[i] * xv4.w;
                }
            }
            __syncthreads();
        }

        const float dcoef = Dparam[h];
#pragma unroll
        for (int i = 0; i < 8; i++) {
            int l = ty * 8 + i;
            float4 xr = *(const float4*)(xs + l * DP + tx * 4);
            float4 o = make_float4(acc[i][0] + dcoef * xr.x, acc[i][1] + dcoef * xr.y,
                                   acc[i][2] + dcoef * xr.z, acc[i][3] + dcoef * xr.w);
            *(float4*)(g_y + (size_t)(c * CSZ + l) * DINTER + h * DP + tx * 4) = o;
        }
    }
    __syncthreads();

    // ---- Phase B: local chunk states (n = tx*8+nj, p = ty*4+pi) ----
    {
        float* const Bsh = work;          // [32][128]
        float* const dec = work + 4096;   // [32]
        const float al = acsS[CSZ - 1];   // == g_alast[c*NH+h]

        float acc[4][8];
#pragma unroll
        for (int i = 0; i < 4; i++)
#pragma unroll
            for (int j = 0; j < 8; j++) acc[i][j] = 0.f;

        for (int l0 = 0; l0 < CSZ; l0 += 32) {
            for (int i = tid; i < 32 * DN / 4; i += 256) {
                int r = i >> 5, q = i & 31;
                *(float4*)(Bsh + r * DN + q * 4) = *(const float4*)(
                    g_xbc + (size_t)(c * CSZ + l0 + r) * DCONV + DINTER + g * DN + q * 4);
            }
            if (tid < 32) {
                int l = l0 + tid;
                dec[tid] = __expf(al - acsS[l]) * dts[l];
            }
            __syncthreads();
#pragma unroll 8
            for (int ll = 0; ll < 32; ll++) {
                float d = dec[ll];
                float4 b0 = *(const float4*)(Bsh + ll * DN + tx * 8);
                float4 b1 = *(const float4*)(Bsh + ll * DN + tx * 8 + 4);
                float bb[8] = {b0.x, b0.y, b0.z, b0.w, b1.x, b1.y, b1.z, b1.w};
                float4 xv = *(const float4*)(xs + (l0 + ll) * DP + ty * 4);
                float xp[4] = {xv.x * d, xv.y * d, xv.z * d, xv.w * d};
#pragma unroll
                for (int pi = 0; pi < 4; pi++)
#pragma unroll
                    for (int nj = 0; nj < 8; nj++) acc[pi][nj] += xp[pi] * bb[nj];
            }
            __syncthreads();
        }
        float* out = g_states + (size_t)(c * NH + h) * DP * DN;
#pragma unroll
        for (int pi = 0; pi < 4; pi++) {
            int p = ty * 4 + pi;
            *(float4*)(out + (size_t)p * DN + tx * 8)     = make_float4(acc[pi][0], acc[pi][1], acc[pi][2], acc[pi][3]);
            *(float4*)(out + (size_t)p * DN + tx * 8 + 4) = make_float4(acc[pi][4], acc[pi][5], acc[pi][6], acc[pi][7]);
        }
    }
}

// ---------------- Inter-chunk scan ----------------
__global__ void prefix_kernel()
{
    int idx = blockIdx.x * blockDim.x + threadIdx.x;
    if (idx >= NH * DP * DN) return;
    int h = idx >> 13;
    float s = 0.f;
#pragma unroll
    for (int c = 0; c < NCH; c++) {
        size_t off = (size_t)c * NH * DP * DN + idx;
        g_prefix[off] = s;
        s = __expf(g_alast[c * NH + h]) * s + g_states[off];
    }
}

// ---------------- Y_off ----------------
__global__ __launch_bounds__(256) void yoff_kernel()
{
    int c = blockIdx.x, h = blockIdx.y, g = h >> 4;
    int tid = threadIdx.x, tx = tid & 15, ty = tid >> 4;
    __shared__ float Cs[CSZ][32];
    __shared__ float Pf[DP][33];
    __shared__ float acsS[CSZ];
    if (tid < CSZ) acsS[tid] = g_acs[(c * NH + h) * CSZ + tid];

    float acc[8][4];
#pragma unroll
    for (int i = 0; i < 8; i++)
#pragma unroll
        for (int j = 0; j < 4; j++) acc[i][j] = 0.f;

    for (int n0 = 0; n0 < DN; n0 += 32) {
        for (int i = tid; i < CSZ * 8; i += 256) {
            int r = i >> 3, q = i & 7;
            *(float4*)&Cs[r][q * 4] = *(const float4*)(
                g_xbc + (size_t)(c * CSZ + r) * DCONV + DINTER + NG * DN + g * DN + n0 + q * 4);
        }
        for (int i = tid; i < DP * 8; i += 256) {
            int r = i >> 3, q = i & 7;
            float4 v = *(const float4*)(
                g_prefix + ((size_t)(c * NH + h) * DP + r) * DN + n0 + q * 4);
            Pf[r][q * 4 + 0] = v.x; Pf[r][q * 4 + 1] = v.y;
            Pf[r][q * 4 + 2] = v.z; Pf[r][q * 4 + 3] = v.w;
        }
        __syncthreads();
#pragma unroll 8
        for (int nn = 0; nn < 32; nn++) {
            float cl[8], pv[4];
#pragma unroll
            for (int i = 0; i < 8; i++) cl[i] = Cs[ty * 8 + i][nn];
#pragma unroll
            for (int j = 0; j < 4; j++) pv[j] = Pf[tx * 4 + j][nn];
#pragma unroll
            for (int i = 0; i < 8; i++)
#pragma unroll
                for (int j = 0; j < 4; j++) acc[i][j] += cl[i] * pv[j];
        }
        __syncthreads();
    }
#pragma unroll
    for (int i = 0; i < 8; i++) {
        int l = ty * 8 + i;
        float e = __expf(acsS[l]);
        float* yp = g_y + (size_t)(c * CSZ + l) * DINTER + h * DP + tx * 4;
        float4 y = *(float4*)yp;
        y.x += e * acc[i][0]; y.y += e * acc[i][1];
        y.z += e * acc[i][2]; y.w += e * acc[i][3];
        *(float4*)yp = y;
    }
}

// ---------------- RMSNorm * norm_w * silu(gate); float4, emits fp16 ----------------
__global__ __launch_bounds__(256) void rms_gate_kernel(const float* __restrict__ norm_w)
{
    int t = blockIdx.x, tid = threadIdx.x;
    const size_t base = (size_t)t * DINTER;
    float ss = 0.f;
    for (int i = tid; i < DINTER / 4; i += 256) {
        float4 v = *(const float4*)(g_y + base + i * 4);
        ss += v.x * v.x + v.y * v.y + v.z * v.z + v.w * v.w;
    }
    __shared__ float red[256];
    red[tid] = ss;
    __syncthreads();
#pragma unroll
    for (int o = 128; o > 0; o >>= 1) {
        if (tid < o) red[tid] += red[tid + o];
        __syncthreads();
    }
    float inv = rsqrtf(red[0] / (float)DINTER + RMS_EPS);
    for (int i = tid; i < DINTER / 4; i += 256) {
        float4 v = *(const float4*)(g_y + base + i * 4);
        float4 w = *(const float4*)(norm_w + i * 4);
        float4 gt = *(const float4*)(g_proj + (size_t)t * DPROJ + i * 4);
        float r0 = v.x * inv * w.x * fast_silu(gt.x);
        float r1 = v.y * inv * w.y * fast_silu(gt.y);
        float r2 = v.z * inv * w.z * fast_silu(gt.z);
        float r3 = v.w * inv * w.w * fast_silu(gt.w);
        __half2 h0 = __floats2half2_rn(r0, r1);
        __half2 h1 = __floats2half2_rn(r2, r3);
        uint2 o;
        o.x = *(uint32_t*)&h0;
        o.y = *(uint32_t*)&h1;
        *(uint2*)(g_yh + base + i * 4) = o;
    }
}

// ---------------- Launch ----------------
extern "C" void kernel_launch(void* const* d_in, const int* in_sizes, int n_in,
                              void* d_out, int out_size)
{
    (void)in_sizes; (void)n_in; (void)out_size;
    const float* hs         = (const float*)d_in[0];
    const float* in_proj_w  = (const float*)d_in[1];
    const float* conv_w     = (const float*)d_in[2];
    const float* conv_b     = (const float*)d_in[3];
    const float* dt_bias    = (const float*)d_in[4];
    const float* A_log      = (const float*)d_in[5];
    const float* Dp         = (const float*)d_in[6];
    const float* norm_w     = (const float*)d_in[7];
    const float* out_proj_w = (const float*)d_in[8];
    float* out = (float*)d_out;

    void *p_proj = nullptr, *p_yh = nullptr, *p_hsth = nullptr, *p_w1th = nullptr, *p_w2th = nullptr;
    cudaGetSymbolAddress(&p_proj, g_proj);
    cudaGetSymbolAddress(&p_yh, g_yh);
    cudaGetSymbolAddress(&p_hsth, g_hsth);
    cudaGetSymbolAddress(&p_w1th, g_w1th);
    cudaGetSymbolAddress(&p_w2th, g_w2th);

    cudaFuncSetAttribute(gemm_f16_kernel, cudaFuncAttributeMaxDynamicSharedMemorySize, GEMM_DSMEM);
    cudaFuncSetAttribute(ydiag_states_kernel, cudaFuncAttributeMaxDynamicSharedMemorySize, YDST_SMEM);

    // side stream + events (host objects; created once, reused; capture-safe fork/join)
    static cudaStream_t s2 = nullptr;
    static cudaEvent_t evA = nullptr, evB = nullptr, evC = nullptr, evD = nullptr;
    if (!s2) {
        cudaStreamCreateWithFlags(&s2, cudaStreamNonBlocking);
        cudaEventCreateWithFlags(&evA, cudaEventDisableTiming);
        cudaEventCreateWithFlags(&evB, cudaEventDisableTiming);
        cudaEventCreateWithFlags(&evC, cudaEventDisableTiming);
        cudaEventCreateWithFlags(&evD, cudaEventDisableTiming);
    }

    // fork: cvt_w2 runs on s2, overlapping GEMM1 (only needed at step 10)
    cudaEventRecord(evA, 0);
    cudaStreamWaitEvent(s2, evA, 0);
    {
        int n4 = DMODEL * DINTER / 4;
        cvt_f16_kernel<<<(n4 + 255) / 256, 256, 0, s2>>>(out_proj_w, (__half*)p_w2th, n4);
    }
    cudaEventRecord(evB, s2);

    // main chain: convert GEMM1 operands
    {
        int n4 = LSEQ * DMODEL / 4;
        cvt_f16_kernel<<<(n4 + 255) / 256, 256>>>(hs, (__half*)p_hsth, n4);
        n4 = DPROJ * DMODEL / 4;
        cvt_f16_kernel<<<(n4 + 255) / 256, 256>>>(in_proj_w, (__half*)p_w1th, n4);
    }

    // 1) in-proj GEMM
    gemm_f16_kernel<<<dim3(LSEQ / 128, DPROJ / 128), 128, GEMM_DSMEM>>>(
        (const __half*)p_hsth, (const __half*)p_w1th, (float*)p_proj, DPROJ, DMODEL);

    // fork: dt_scan (depends only on g_proj) overlaps conv + cb
    cudaEventRecord(evC, 0);
    cudaStreamWaitEvent(s2, evC, 0);
    dt_scan_kernel<<<dim3(NCH, NH), CSZ, 0, s2>>>(dt_bias, A_log);
    cudaEventRecord(evD, s2);

    // 2) conv + silu
    conv_silu_kernel<<<(LSEQ * (DCONV / 4) + 255) / 256, 256>>>(conv_w, conv_b);
    // 4) C·B^T
    cb_kernel<<<dim3(NCH, NG), 256>>>();

    // join dt_scan before fused ydiag+states
    cudaStreamWaitEvent(0, evD, 0);
    // 5+6) fused intra-chunk output + local chunk states
    ydiag_states_kernel<<<dim3(NCH, NH), 256, YDST_SMEM>>>(Dp);
    // 7) inter-chunk scan
    prefix_kernel<<<(NH * DP * DN + 255) / 256, 256>>>();
    // 8) off-diagonal output
    yoff_kernel<<<dim3(NCH, NH), 256>>>();
    // 9) gated RMSNorm
    rms_gate_kernel<<<LSEQ, 256>>>(norm_w);

    // join cvt_w2 before out-proj GEMM
    cudaStreamWaitEvent(0, evB, 0);
    // 10) out-proj GEMM
    gemm_f16_kernel<<<dim3(LSEQ / 128, DMODEL / 128), 128, GEMM_DSMEM>>>(
        (const __half*)p_yh, (const __half*)p_w2th, out, DMODEL, DINTER);
}